// round 13
// baseline (speedup 1.0000x reference)
#include <cuda_runtime.h>
#include <cuda_bf16.h>
#include <cstdint>

// Problem constants
#define SEQ     512
#define BATCH   256
#define IN_DIM  256
#define HID_DIM 256
#define NQ      8
#define MLP_HID 128
#define CDIM    (IN_DIM + HID_DIM)
#define ROWS    (SEQ * BATCH)          // 131072

// ---------------------------------------------------------------------------
// Scratch (static __device__ — no allocations allowed)
// ---------------------------------------------------------------------------
__device__ float4 g_A4[(size_t)ROWS * (MLP_HID / 4)];  // A[t,b,m] = x@W1x + b1  (64 MB)
__device__ float4 g_G4[(size_t)ROWS];                   // G[t,b] = (f,i,g,o) pre-acts (2 MB)
__device__ float  g_w1h[MLP_HID];                       // colsum of W1[256:512]
__device__ float  g_s4[4];                              // sums of Wf/Wi/Wg/Wo[256:512]
__device__ float  g_h[ROWS];                            // h scalar per (t,b)
__device__ float  g_c[BATCH];                           // final c per batch

// ---------------------------------------------------------------------------
// Math helpers
// ---------------------------------------------------------------------------
__device__ __forceinline__ float sigf(float x) {
    return 1.0f / (1.0f + __expf(-x));
}
__device__ __forceinline__ float tanh_fast(float x) {
    // tanh(x) = 1 - 2/(e^{2x}+1); saturates correctly at +-inf
    return 1.0f - 2.0f / (__expf(2.0f * x) + 1.0f);
}

// ---------------------------------------------------------------------------
// Kernel 1: tiny prep — w1h[m] = sum_d W1[256+d][m];  s4 = sums of gate weights
// ---------------------------------------------------------------------------
__global__ void prep_kernel(const float* __restrict__ W1,
                            const float* __restrict__ Wf, const float* __restrict__ Wi,
                            const float* __restrict__ Wg, const float* __restrict__ Wo)
{
    int tid = threadIdx.x;
    if (tid < MLP_HID) {
        float s = 0.f;
        #pragma unroll 8
        for (int d = 0; d < HID_DIM; d++)
            s += W1[(size_t)(IN_DIM + d) * MLP_HID + tid];
        g_w1h[tid] = s;
    } else if (tid < MLP_HID + 4) {
        const float* W = (tid == MLP_HID) ? Wf : (tid == MLP_HID + 1) ? Wi
                        : (tid == MLP_HID + 2) ? Wg : Wo;
        float s = 0.f;
        #pragma unroll 8
        for (int d = 0; d < HID_DIM; d++) s += W[IN_DIM + d];
        g_s4[tid - MLP_HID] = s;
    }
}

// ---------------------------------------------------------------------------
// Kernel 2: gate pre-activations G[row] = (x@Wfx+bf, x@Wix+bi, x@Wgx+bg, x@Wox+bo)
// one warp per row (256 contiguous floats of x). 8 rows / CTA.
// ---------------------------------------------------------------------------
__global__ __launch_bounds__(256) void gate_kernel(
    const float* __restrict__ x,
    const float* __restrict__ Wf, const float* __restrict__ Wi,
    const float* __restrict__ Wg, const float* __restrict__ Wo,
    const float* __restrict__ bf, const float* __restrict__ bi,
    const float* __restrict__ bg, const float* __restrict__ bo)
{
    __shared__ float w[4][IN_DIM];
    int tid = threadIdx.x;
    w[0][tid] = Wf[tid]; w[1][tid] = Wi[tid]; w[2][tid] = Wg[tid]; w[3][tid] = Wo[tid];
    __syncthreads();

    int warp = tid >> 5, lane = tid & 31;
    int row = blockIdx.x * 8 + warp;
    const float4* xr = (const float4*)(x + (size_t)row * IN_DIM);
    float4 x0 = xr[lane];       // elements lane*4 .. +3
    float4 x1 = xr[32 + lane];  // elements 128 + lane*4 .. +3

    float s[4];
    #pragma unroll
    for (int gi = 0; gi < 4; gi++) {
        const float4* wv = (const float4*)w[gi];
        float4 w0 = wv[lane];
        float4 w1 = wv[32 + lane];
        float a = x0.x * w0.x + x0.y * w0.y + x0.z * w0.z + x0.w * w0.w
                + x1.x * w1.x + x1.y * w1.y + x1.z * w1.z + x1.w * w1.w;
        #pragma unroll
        for (int d = 16; d >= 1; d >>= 1)
            a += __shfl_xor_sync(0xffffffffu, a, d);
        s[gi] = a;
    }
    if (lane == 0) {
        float4 o;
        o.x = s[0] + bf[0]; o.y = s[1] + bi[0];
        o.z = s[2] + bg[0]; o.w = s[3] + bo[0];
        g_G4[row] = o;
    }
}

// ---------------------------------------------------------------------------
// Kernel 3: GEMM  A[row][m] = x[row] @ W1x + b1   (M=131072, K=256, N=128)
// 128x128 CTA tile (single N tile!), BK=16, 256 threads, 8x8 per thread.
// Inner product uses packed fma.rn.f32x2 (2 MACs / instruction).
// ---------------------------------------------------------------------------
#define BM 128
#define BN 128
#define BK 16

__global__ __launch_bounds__(256) void gemm_kernel(
    const float* __restrict__ A, const float* __restrict__ W1,
    const float* __restrict__ b1)
{
    __shared__ float As[BK][BM + 4];   // transposed A tile
    __shared__ float Bs[BK][BN];

    int tid  = threadIdx.x;
    int row0 = blockIdx.x * BM;
    int tx = tid & 15;            // 0..15 -> N
    int ty = tid >> 4;            // 0..15 -> M
    int arow  = tid >> 2;         // 0..63
    int acol4 = (tid & 3) * 4;    // 0,4,8,12

    unsigned long long acc2[8][4];
    #pragma unroll
    for (int i = 0; i < 8; i++)
        #pragma unroll
        for (int j = 0; j < 4; j++) acc2[i][j] = 0ull;

    for (int k0 = 0; k0 < CDIM / 2; k0 += BK) {   // K = 256
        float4 a0 = *(const float4*)(A + (size_t)(row0 + arow) * IN_DIM + k0 + acol4);
        float4 a1 = *(const float4*)(A + (size_t)(row0 + arow + 64) * IN_DIM + k0 + acol4);
        float4 bv0 = *(const float4*)(W1 + (size_t)(k0 + (tid >> 5)) * MLP_HID + (tid & 31) * 4);
        float4 bv1 = *(const float4*)(W1 + (size_t)(k0 + 8 + (tid >> 5)) * MLP_HID + (tid & 31) * 4);
        __syncthreads();
        As[acol4 + 0][arow] = a0.x; As[acol4 + 1][arow] = a0.y;
        As[acol4 + 2][arow] = a0.z; As[acol4 + 3][arow] = a0.w;
        As[acol4 + 0][arow + 64] = a1.x; As[acol4 + 1][arow + 64] = a1.y;
        As[acol4 + 2][arow + 64] = a1.z; As[acol4 + 3][arow + 64] = a1.w;
        *(float4*)&Bs[tid >> 5][(tid & 31) * 4]     = bv0;
        *(float4*)&Bs[8 + (tid >> 5)][(tid & 31) * 4] = bv1;
        __syncthreads();

        #pragma unroll
        for (int k = 0; k < BK; k++) {
            float af[8];
            *(float4*)&af[0] = *(const float4*)&As[k][ty * 8];
            *(float4*)&af[4] = *(const float4*)&As[k][ty * 8 + 4];
            float4 bl0 = *(const float4*)&Bs[k][tx * 8];
            float4 bl1 = *(const float4*)&Bs[k][tx * 8 + 4];
            unsigned long long bp[4];
            asm("mov.b64 %0, {%1, %2};" : "=l"(bp[0]) : "f"(bl0.x), "f"(bl0.y));
            asm("mov.b64 %0, {%1, %2};" : "=l"(bp[1]) : "f"(bl0.z), "f"(bl0.w));
            asm("mov.b64 %0, {%1, %2};" : "=l"(bp[2]) : "f"(bl1.x), "f"(bl1.y));
            asm("mov.b64 %0, {%1, %2};" : "=l"(bp[3]) : "f"(bl1.z), "f"(bl1.w));
            #pragma unroll
            for (int i = 0; i < 8; i++) {
                unsigned long long ad;
                asm("mov.b64 %0, {%1, %1};" : "=l"(ad) : "f"(af[i]));
                #pragma unroll
                for (int j = 0; j < 4; j++)
                    asm("fma.rn.f32x2 %0, %1, %2, %0;"
                        : "+l"(acc2[i][j]) : "l"(ad), "l"(bp[j]));
            }
        }
    }

    // epilogue: add b1, store
    float badd[8];
    *(float4*)&badd[0] = *(const float4*)(b1 + tx * 8);
    *(float4*)&badd[4] = *(const float4*)(b1 + tx * 8 + 4);
    float* C = (float*)g_A4;
    #pragma unroll
    for (int i = 0; i < 8; i++) {
        int row = row0 + ty * 8 + i;
        float o[8];
        #pragma unroll
        for (int j = 0; j < 4; j++) {
            float lo, hi;
            asm("mov.b64 {%0, %1}, %2;" : "=f"(lo), "=f"(hi) : "l"(acc2[i][j]));
            o[2 * j]     = lo + badd[2 * j];
            o[2 * j + 1] = hi + badd[2 * j + 1];
        }
        *(float4*)(C + (size_t)row * MLP_HID + tx * 8)     = *(float4*)&o[0];
        *(float4*)(C + (size_t)row * MLP_HID + tx * 8 + 4) = *(float4*)&o[4];
    }
}

// ---------------------------------------------------------------------------
// Kernel 4: recurrence — one warp per batch element. W2 column lives in regs.
// ---------------------------------------------------------------------------
__global__ __launch_bounds__(32, 1) void recur_kernel(
    const float* __restrict__ W2, const float* __restrict__ b2)
{
    int b    = blockIdx.x;
    int lane = threadIdx.x;
    __shared__ float4 h1s[32];

    // W2[:,lane] into registers (128 regs)
    float w2r[MLP_HID];
    #pragma unroll
    for (int m = 0; m < MLP_HID; m++) w2r[m] = W2[m * 32 + lane];
    float bq = b2[lane];

    float4 wh = ((const float4*)g_w1h)[lane];
    float sf = g_s4[0], si = g_s4[1], sg = g_s4[2], so = g_s4[3];

    const float4* Ab = g_A4 + (size_t)b * 32 + lane;   // stride per t: 256*32 float4
    const float4* Gb = g_G4 + b;                        // stride per t: 256

    float h = 0.f, c = 0.f;
    float4 a  = Ab[0];
    float4 g4 = Gb[0];

    const unsigned FULL = 0xffffffffu;

    for (int t = 0; t < SEQ; t++) {
        // h1 = relu(A + h*w1h)
        float4 v;
        v.x = fmaxf(fmaf(h, wh.x, a.x), 0.f);
        v.y = fmaxf(fmaf(h, wh.y, a.y), 0.f);
        v.z = fmaxf(fmaf(h, wh.z, a.z), 0.f);
        v.w = fmaxf(fmaf(h, wh.w, a.w), 0.f);
        h1s[lane] = v;
        __syncwarp();

        // prefetch next step (independent of h)
        int tn = (t + 1 < SEQ) ? (t + 1) : (SEQ - 1);
        float4 a_n = Ab[(size_t)tn * (BATCH * 32)];
        float4 g_n = Gb[(size_t)tn * BATCH];

        // q[lane] = h1 . W2[:,lane]
        float q0 = 0.f, q1 = 0.f, q2 = 0.f, q3 = 0.f;
        #pragma unroll
        for (int mm = 0; mm < 32; mm++) {
            float4 hv = h1s[mm];
            q0 = fmaf(hv.x, w2r[4 * mm + 0], q0);
            q1 = fmaf(hv.y, w2r[4 * mm + 1], q1);
            q2 = fmaf(hv.z, w2r[4 * mm + 2], q2);
            q3 = fmaf(hv.w, w2r[4 * mm + 3], q3);
        }
        __syncwarp();
        float q = (q0 + q1) + (q2 + q3) + bq;

        // qgate: mean of cumprod(cos(theta)) over 8-lane segments
        float p = __cosf(q);
        float u;
        u = __shfl_up_sync(FULL, p, 1, 8); if ((lane & 7) >= 1) p *= u;
        u = __shfl_up_sync(FULL, p, 2, 8); if ((lane & 7) >= 2) p *= u;
        u = __shfl_up_sync(FULL, p, 4, 8); if ((lane & 7) >= 4) p *= u;
        float s = p;
        s += __shfl_xor_sync(FULL, s, 1);
        s += __shfl_xor_sync(FULL, s, 2);
        s += __shfl_xor_sync(FULL, s, 4);
        s *= 0.125f;
        float qf = __shfl_sync(FULL, s, 0);
        float qi = __shfl_sync(FULL, s, 8);
        float qg = __shfl_sync(FULL, s, 16);
        float qo = __shfl_sync(FULL, s, 24);

        // gates (ALPHA = 0.5)
        float f  = 0.5f * (sigf(fmaf(h, sf, g4.x)) + sigf(qf));
        float i_ = 0.5f * (sigf(fmaf(h, si, g4.y)) + sigf(qi));
        float gg = 0.5f * (tanh_fast(fmaf(h, sg, g4.z)) + tanh_fast(qg));
        float o  = 0.5f * (sigf(fmaf(h, so, g4.w)) + sigf(qo));

        c = f * c + i_ * gg;
        h = o * tanh_fast(c);

        if (lane == 0) g_h[t * BATCH + b] = h;
        a = a_n; g4 = g_n;
    }
    if (lane == 0) g_c[b] = c;
}

// ---------------------------------------------------------------------------
// Kernel 5: broadcast scalar h/c to all HID_DIM columns of the output
// layout: outputs[SEQ][BATCH][HID] , hx[BATCH][HID] , cx[BATCH][HID]
// ---------------------------------------------------------------------------
__global__ void bcast_kernel(float4* __restrict__ out, int n4, int out_size)
{
    int i = blockIdx.x * blockDim.x + threadIdx.x;
    if (i < n4) {
        int row = i >> 6;                 // 64 float4 per 256-col row
        float v;
        if (row < ROWS)                   v = g_h[row];
        else if (row < ROWS + BATCH)      v = g_h[(SEQ - 1) * BATCH + (row - ROWS)];
        else                              v = g_c[row - ROWS - BATCH];
        out[i] = make_float4(v, v, v, v);
    }
    // scalar tail (out_size not multiple of 4 — defensive)
    if (i == 0) {
        float* of = (float*)out;
        for (int e = n4 * 4; e < out_size; e++) {
            int row = e >> 8;
            float v;
            if (row < ROWS)              v = g_h[row];
            else if (row < ROWS + BATCH) v = g_h[(SEQ - 1) * BATCH + (row - ROWS)];
            else                         v = g_c[row - ROWS - BATCH];
            of[e] = v;
        }
    }
}

// ---------------------------------------------------------------------------
// Launch
// ---------------------------------------------------------------------------
extern "C" void kernel_launch(void* const* d_in, const int* in_sizes, int n_in,
                              void* d_out, int out_size)
{
    const float* inputs = (const float*)d_in[0];
    const float* W1 = (const float*)d_in[1];
    const float* b1 = (const float*)d_in[2];
    const float* W2 = (const float*)d_in[3];
    const float* b2 = (const float*)d_in[4];
    const float* Wf = (const float*)d_in[5];  const float* bf = (const float*)d_in[6];
    const float* Wi = (const float*)d_in[7];  const float* bi = (const float*)d_in[8];
    const float* Wg = (const float*)d_in[9];  const float* bg = (const float*)d_in[10];
    const float* Wo = (const float*)d_in[11]; const float* bo = (const float*)d_in[12];

    prep_kernel<<<1, 160>>>(W1, Wf, Wi, Wg, Wo);
    gate_kernel<<<ROWS / 8, 256>>>(inputs, Wf, Wi, Wg, Wo, bf, bi, bg, bo);
    gemm_kernel<<<ROWS / BM, 256>>>(inputs, W1, b1);
    recur_kernel<<<BATCH, 32>>>(W2, b2);

    int n4 = out_size >> 2;
    int nb = (n4 + 255) / 256;
    if (nb < 1) nb = 1;
    bcast_kernel<<<nb, 256>>>((float4*)d_out, n4, out_size);
}

// round 14
// speedup vs baseline: 1.2361x; 1.2361x over previous
#include <cuda_runtime.h>
#include <cuda_bf16.h>
#include <cstdint>

// Problem constants
#define SEQ     512
#define BATCH   256
#define IN_DIM  256
#define HID_DIM 256
#define NQ      8
#define MLP_HID 128
#define CDIM    (IN_DIM + HID_DIM)
#define ROWS    (SEQ * BATCH)          // 131072

typedef unsigned long long ull;

// ---------------------------------------------------------------------------
// Scratch (static __device__ — no allocations allowed)
// ---------------------------------------------------------------------------
__device__ float4 g_A4[(size_t)ROWS * (MLP_HID / 4)];  // A[t,b,m] = x@W1x + b1  (64 MB)
__device__ float4 g_G4[(size_t)ROWS];                   // G[t,b] = (f,i,g,o) pre-acts (2 MB)
__device__ float  g_w1h[MLP_HID];                       // colsum of W1[256:512]
__device__ float  g_s4[4];                              // sums of Wf/Wi/Wg/Wo[256:512]
__device__ float  g_h[ROWS];                            // h scalar per (t,b)
__device__ float  g_c[BATCH];                           // final c per batch

// ---------------------------------------------------------------------------
// Math helpers
// ---------------------------------------------------------------------------
__device__ __forceinline__ float sig01(float x) {
    // 1 / (1 + e^{-x})  via approx exp + approx rcp
    return __fdividef(1.0f, 1.0f + __expf(-x));
}
__device__ __forceinline__ float tanh_fast(float x) {
    return 1.0f - 2.0f * __fdividef(1.0f, __expf(2.0f * x) + 1.0f);
}
__device__ __forceinline__ void fma2(ull& acc, ull a, ull b) {
    asm("fma.rn.f32x2 %0, %1, %2, %0;" : "+l"(acc) : "l"(a), "l"(b));
}
__device__ __forceinline__ ull add2(ull a, ull b) {
    ull r; asm("add.rn.f32x2 %0, %1, %2;" : "=l"(r) : "l"(a), "l"(b)); return r;
}

// ---------------------------------------------------------------------------
// Kernel 1: tiny prep — w1h[m] = sum_d W1[256+d][m];  s4 = sums of gate weights
// ---------------------------------------------------------------------------
__global__ void prep_kernel(const float* __restrict__ W1,
                            const float* __restrict__ Wf, const float* __restrict__ Wi,
                            const float* __restrict__ Wg, const float* __restrict__ Wo)
{
    int tid = threadIdx.x;
    if (tid < MLP_HID) {
        float s = 0.f;
        #pragma unroll 8
        for (int d = 0; d < HID_DIM; d++)
            s += W1[(size_t)(IN_DIM + d) * MLP_HID + tid];
        g_w1h[tid] = s;
    } else if (tid < MLP_HID + 4) {
        const float* W = (tid == MLP_HID) ? Wf : (tid == MLP_HID + 1) ? Wi
                        : (tid == MLP_HID + 2) ? Wg : Wo;
        float s = 0.f;
        #pragma unroll 8
        for (int d = 0; d < HID_DIM; d++) s += W[IN_DIM + d];
        g_s4[tid - MLP_HID] = s;
    }
}

// ---------------------------------------------------------------------------
// Kernel 2: gate pre-activations G[row] = (x@Wfx+bf, x@Wix+bi, x@Wgx+bg, x@Wox+bo)
// ---------------------------------------------------------------------------
__global__ __launch_bounds__(256) void gate_kernel(
    const float* __restrict__ x,
    const float* __restrict__ Wf, const float* __restrict__ Wi,
    const float* __restrict__ Wg, const float* __restrict__ Wo,
    const float* __restrict__ bf, const float* __restrict__ bi,
    const float* __restrict__ bg, const float* __restrict__ bo)
{
    __shared__ float w[4][IN_DIM];
    int tid = threadIdx.x;
    w[0][tid] = Wf[tid]; w[1][tid] = Wi[tid]; w[2][tid] = Wg[tid]; w[3][tid] = Wo[tid];
    __syncthreads();

    int warp = tid >> 5, lane = tid & 31;
    int row = blockIdx.x * 8 + warp;
    const float4* xr = (const float4*)(x + (size_t)row * IN_DIM);
    float4 x0 = xr[lane];
    float4 x1 = xr[32 + lane];

    float s[4];
    #pragma unroll
    for (int gi = 0; gi < 4; gi++) {
        const float4* wv = (const float4*)w[gi];
        float4 w0 = wv[lane];
        float4 w1 = wv[32 + lane];
        float a = x0.x * w0.x + x0.y * w0.y + x0.z * w0.z + x0.w * w0.w
                + x1.x * w1.x + x1.y * w1.y + x1.z * w1.z + x1.w * w1.w;
        #pragma unroll
        for (int d = 16; d >= 1; d >>= 1)
            a += __shfl_xor_sync(0xffffffffu, a, d);
        s[gi] = a;
    }
    if (lane == 0) {
        float4 o;
        o.x = s[0] + bf[0]; o.y = s[1] + bi[0];
        o.z = s[2] + bg[0]; o.w = s[3] + bo[0];
        g_G4[row] = o;
    }
}

// ---------------------------------------------------------------------------
// Kernel 3: GEMM  A[row][m] = x[row] @ W1x + b1   (M=131072, K=256, N=128)
// ---------------------------------------------------------------------------
#define BM 128
#define BN 128
#define BK 16

__global__ __launch_bounds__(256) void gemm_kernel(
    const float* __restrict__ A, const float* __restrict__ W1,
    const float* __restrict__ b1)
{
    __shared__ float As[BK][BM + 4];
    __shared__ float Bs[BK][BN];

    int tid  = threadIdx.x;
    int row0 = blockIdx.x * BM;
    int tx = tid & 15;
    int ty = tid >> 4;
    int arow  = tid >> 2;
    int acol4 = (tid & 3) * 4;

    ull acc2[8][4];
    #pragma unroll
    for (int i = 0; i < 8; i++)
        #pragma unroll
        for (int j = 0; j < 4; j++) acc2[i][j] = 0ull;

    for (int k0 = 0; k0 < CDIM / 2; k0 += BK) {
        float4 a0 = *(const float4*)(A + (size_t)(row0 + arow) * IN_DIM + k0 + acol4);
        float4 a1 = *(const float4*)(A + (size_t)(row0 + arow + 64) * IN_DIM + k0 + acol4);
        float4 bv0 = *(const float4*)(W1 + (size_t)(k0 + (tid >> 5)) * MLP_HID + (tid & 31) * 4);
        float4 bv1 = *(const float4*)(W1 + (size_t)(k0 + 8 + (tid >> 5)) * MLP_HID + (tid & 31) * 4);
        __syncthreads();
        As[acol4 + 0][arow] = a0.x; As[acol4 + 1][arow] = a0.y;
        As[acol4 + 2][arow] = a0.z; As[acol4 + 3][arow] = a0.w;
        As[acol4 + 0][arow + 64] = a1.x; As[acol4 + 1][arow + 64] = a1.y;
        As[acol4 + 2][arow + 64] = a1.z; As[acol4 + 3][arow + 64] = a1.w;
        *(float4*)&Bs[tid >> 5][(tid & 31) * 4]     = bv0;
        *(float4*)&Bs[8 + (tid >> 5)][(tid & 31) * 4] = bv1;
        __syncthreads();

        #pragma unroll
        for (int k = 0; k < BK; k++) {
            float af[8];
            *(float4*)&af[0] = *(const float4*)&As[k][ty * 8];
            *(float4*)&af[4] = *(const float4*)&As[k][ty * 8 + 4];
            float4 bl0 = *(const float4*)&Bs[k][tx * 8];
            float4 bl1 = *(const float4*)&Bs[k][tx * 8 + 4];
            ull bp[4];
            asm("mov.b64 %0, {%1, %2};" : "=l"(bp[0]) : "f"(bl0.x), "f"(bl0.y));
            asm("mov.b64 %0, {%1, %2};" : "=l"(bp[1]) : "f"(bl0.z), "f"(bl0.w));
            asm("mov.b64 %0, {%1, %2};" : "=l"(bp[2]) : "f"(bl1.x), "f"(bl1.y));
            asm("mov.b64 %0, {%1, %2};" : "=l"(bp[3]) : "f"(bl1.z), "f"(bl1.w));
            #pragma unroll
            for (int i = 0; i < 8; i++) {
                ull ad;
                asm("mov.b64 %0, {%1, %1};" : "=l"(ad) : "f"(af[i]));
                #pragma unroll
                for (int j = 0; j < 4; j++)
                    asm("fma.rn.f32x2 %0, %1, %2, %0;"
                        : "+l"(acc2[i][j]) : "l"(ad), "l"(bp[j]));
            }
        }
    }

    float badd[8];
    *(float4*)&badd[0] = *(const float4*)(b1 + tx * 8);
    *(float4*)&badd[4] = *(const float4*)(b1 + tx * 8 + 4);
    float* C = (float*)g_A4;
    #pragma unroll
    for (int i = 0; i < 8; i++) {
        int row = row0 + ty * 8 + i;
        float o[8];
        #pragma unroll
        for (int j = 0; j < 4; j++) {
            float lo, hi;
            asm("mov.b64 {%0, %1}, %2;" : "=f"(lo), "=f"(hi) : "l"(acc2[i][j]));
            o[2 * j]     = lo + badd[2 * j];
            o[2 * j + 1] = hi + badd[2 * j + 1];
        }
        *(float4*)(C + (size_t)row * MLP_HID + tx * 8)     = *(float4*)&o[0];
        *(float4*)(C + (size_t)row * MLP_HID + tx * 8 + 4) = *(float4*)&o[4];
    }
}

// ---------------------------------------------------------------------------
// Kernel 4: recurrence — one warp per batch element, latency-optimized.
//  - dot product in fma.rn.f32x2 (64 instr instead of 128)
//  - cumprod/mean via Horner (7 dependent FMA) instead of shuffle cascade
//  - one gate per lane-group (lane&3) -> no redundant MUFU storm
//  - single __syncwarp per step; 2-step-deep global prefetch
// ---------------------------------------------------------------------------
__global__ __launch_bounds__(32, 1) void recur_kernel(
    const float* __restrict__ W2, const float* __restrict__ b2)
{
    int b    = blockIdx.x;
    int lane = threadIdx.x;
    __shared__ float4 h1s[32];

    // pack W2 column `lane` as 64 f32x2 pairs: (row 2m, row 2m+1)
    ull w2p[64];
    #pragma unroll
    for (int m = 0; m < 64; m++) {
        float lo = W2[(size_t)(2 * m) * 32 + lane];
        float hi = W2[(size_t)(2 * m + 1) * 32 + lane];
        asm("mov.b64 %0, {%1, %2};" : "=l"(w2p[m]) : "f"(lo), "f"(hi));
    }
    float bq = b2[lane];
    float4 wh = ((const float4*)g_w1h)[lane];

    // per-lane gate role: 0=f(sig) 1=i(sig) 2=g(tanh) 3=o(sig)
    int   gsel     = lane & 3;
    float s_sel    = g_s4[gsel];
    float preScale = (gsel == 2) ? 2.f : 1.f;   // tanh(x) = 2*sig(2x) - 1
    float outMul   = (gsel == 2) ? 2.f : 1.f;
    float outAdd   = (gsel == 2) ? -1.f : 0.f;

    const float4* Ab = g_A4 + (size_t)b * 32 + lane;   // stride per t: BATCH*32 float4
    const float4* Gb = g_G4 + b;                        // stride per t: BATCH

    float h = 0.f, c = 0.f;
    float4 a0 = Ab[0];
    float4 a1 = Ab[(size_t)(BATCH * 32)];
    float4 g0 = Gb[0];
    float4 g1 = Gb[BATCH];

    const unsigned FULL = 0xffffffffu;

    for (int t = 0; t < SEQ; t++) {
        float4 a   = a0;
        float4 gg4 = g0;
        a0 = a1; g0 = g1;
        int tn = (t + 2 < SEQ) ? (t + 2) : (SEQ - 1);
        a1 = Ab[(size_t)tn * (BATCH * 32)];
        g1 = Gb[(size_t)tn * BATCH];

        // classical gate pre-activation (depends only on h) — start its MUFUs early
        float gc = (gsel == 0) ? gg4.x : (gsel == 1) ? gg4.y : (gsel == 2) ? gg4.z : gg4.w;
        float pre = fmaf(h, s_sel, gc);
        float vc  = fmaf(outMul, sig01(preScale * pre), outAdd);

        // h1 = relu(A + h*w1h)
        float4 v;
        v.x = fmaxf(fmaf(h, wh.x, a.x), 0.f);
        v.y = fmaxf(fmaf(h, wh.y, a.y), 0.f);
        v.z = fmaxf(fmaf(h, wh.z, a.z), 0.f);
        v.w = fmaxf(fmaf(h, wh.w, a.w), 0.f);
        h1s[lane] = v;
        __syncwarp();

        // q[lane] = h1 . W2[:,lane]  in packed f32x2
        ull acc0 = 0ull, acc1 = 0ull, acc2 = 0ull, acc3 = 0ull;
        const ulonglong2* hp = (const ulonglong2*)h1s;
        #pragma unroll
        for (int mm = 0; mm < 32; mm += 2) {
            ulonglong2 hv0 = hp[mm];
            ulonglong2 hv1 = hp[mm + 1];
            fma2(acc0, hv0.x, w2p[2 * mm + 0]);
            fma2(acc1, hv0.y, w2p[2 * mm + 1]);
            fma2(acc2, hv1.x, w2p[2 * mm + 2]);
            fma2(acc3, hv1.y, w2p[2 * mm + 3]);
        }
        ull s02 = add2(acc0, acc2);
        ull s13 = add2(acc1, acc3);
        ull ssum = add2(s02, s13);
        float qlo, qhi;
        asm("mov.b64 {%0, %1}, %2;" : "=f"(qlo), "=f"(qhi) : "l"(ssum));
        float q = (qlo + qhi) + bq;

        // cos per lane; gather my gate's 8 thetas via independent shuffles
        float cv = __cosf(q);
        float cc[8];
        #pragma unroll
        for (int j = 0; j < 8; j++)
            cc[j] = __shfl_sync(FULL, cv, 8 * gsel + j);

        // mean(cumprod) via Horner: S = c0(1 + c1(1 + ... (1 + c7)))
        float tt = cc[7];
        #pragma unroll
        for (int j = 6; j >= 0; j--)
            tt = fmaf(cc[j], tt, cc[j]);
        float qm = tt * 0.125f;

        float vq   = fmaf(outMul, sig01(preScale * qm), outAdd);
        float gate = 0.5f * (vc + vq);

        float f  = __shfl_sync(FULL, gate, 0);
        float i_ = __shfl_sync(FULL, gate, 1);
        float gg = __shfl_sync(FULL, gate, 2);
        float oo = __shfl_sync(FULL, gate, 3);

        c = fmaf(f, c, i_ * gg);
        h = oo * tanh_fast(c);

        if (lane == 0) g_h[t * BATCH + b] = h;
    }
    if (lane == 0) g_c[b] = c;
}

// ---------------------------------------------------------------------------
// Kernel 5: broadcast scalar h/c to all HID_DIM columns of the output
// ---------------------------------------------------------------------------
__global__ void bcast_kernel(float4* __restrict__ out, int n4, int out_size)
{
    int i = blockIdx.x * blockDim.x + threadIdx.x;
    if (i < n4) {
        int row = i >> 6;
        float v;
        if (row < ROWS)                   v = g_h[row];
        else if (row < ROWS + BATCH)      v = g_h[(SEQ - 1) * BATCH + (row - ROWS)];
        else                              v = g_c[row - ROWS - BATCH];
        out[i] = make_float4(v, v, v, v);
    }
    if (i == 0) {
        float* of = (float*)out;
        for (int e = n4 * 4; e < out_size; e++) {
            int row = e >> 8;
            float v;
            if (row < ROWS)              v = g_h[row];
            else if (row < ROWS + BATCH) v = g_h[(SEQ - 1) * BATCH + (row - ROWS)];
            else                         v = g_c[row - ROWS - BATCH];
            of[e] = v;
        }
    }
}

// ---------------------------------------------------------------------------
// Launch
// ---------------------------------------------------------------------------
extern "C" void kernel_launch(void* const* d_in, const int* in_sizes, int n_in,
                              void* d_out, int out_size)
{
    const float* inputs = (const float*)d_in[0];
    const float* W1 = (const float*)d_in[1];
    const float* b1 = (const float*)d_in[2];
    const float* W2 = (const float*)d_in[3];
    const float* b2 = (const float*)d_in[4];
    const float* Wf = (const float*)d_in[5];  const float* bf = (const float*)d_in[6];
    const float* Wi = (const float*)d_in[7];  const float* bi = (const float*)d_in[8];
    const float* Wg = (const float*)d_in[9];  const float* bg = (const float*)d_in[10];
    const float* Wo = (const float*)d_in[11]; const float* bo = (const float*)d_in[12];

    prep_kernel<<<1, 160>>>(W1, Wf, Wi, Wg, Wo);
    gate_kernel<<<ROWS / 8, 256>>>(inputs, Wf, Wi, Wg, Wo, bf, bi, bg, bo);
    gemm_kernel<<<ROWS / BM, 256>>>(inputs, W1, b1);
    recur_kernel<<<BATCH, 32>>>(W2, b2);

    int n4 = out_size >> 2;
    int nb = (n4 + 255) / 256;
    if (nb < 1) nb = 1;
    bcast_kernel<<<nb, 256>>>((float4*)d_out, n4, out_size);
}